// round 9
// baseline (speedup 1.0000x reference)
#include <cuda_runtime.h>
#include <cstdint>

// Problem constants
#define TQ     8192      // T/2 output positions
#define DM     768       // model dim
#define NBINS  1024      // codebook entries
#define TIN    16384     // input T
#define KCONV  1536      // conv GEMM K = D*2
#define NKB1   96        // conv K chunks (1536/16)
#define NKB2   48        // dist K chunks (768/16)

typedef unsigned int u32;

// ---------------------------------------------------------------------------
// Scratch (__device__ globals; no allocation)
// g_Wfrag / g_CBfrag: B operands pre-split to TF32 (hi, mid) AND pre-arranged
// in mma.m16n8k8 B-fragment order, so kernel staging is a contiguous copy.
// Layout per (nb, kb): 4096 floats = [part(2)][k8(2)][nt(16)][lane(32)][2]
// ---------------------------------------------------------------------------
__device__ float g_Wfrag [6 * NKB1 * 4096];   // 9.4 MB
__device__ float g_CBfrag[8 * NKB2 * 4096];   // 6.3 MB
__device__ float g_X[TQ * DM];                // conv output, plain [m][d] (25 MB)
__device__ float g_cnorm[NBINS];
__device__ float g_pmin[TQ * 8];
__device__ int   g_pidx[TQ * 8];

// ---------------------------------------------------------------------------
// TF32 helpers (family-agnostic PTX only — target is plain sm_103!)
// ---------------------------------------------------------------------------
__device__ __forceinline__ void tf32_split(float x, float& h, float& m) {
    u32 hu, mu;
    asm("cvt.rna.tf32.f32 %0, %1;" : "=r"(hu) : "f"(x));
    h = __uint_as_float(hu);
    float r = x - h;
    asm("cvt.rna.tf32.f32 %0, %1;" : "=r"(mu) : "f"(r));
    m = __uint_as_float(mu);
}

__device__ __forceinline__ void mma8(float* d, const u32* a, const u32* b) {
    asm volatile(
        "mma.sync.aligned.m16n8k8.row.col.f32.tf32.tf32.f32 "
        "{%0,%1,%2,%3}, {%4,%5,%6,%7}, {%8,%9}, {%0,%1,%2,%3};"
        : "+f"(d[0]), "+f"(d[1]), "+f"(d[2]), "+f"(d[3])
        : "r"(a[0]), "r"(a[1]), "r"(a[2]), "r"(a[3]), "r"(b[0]), "r"(b[1]));
}

// A-fragment smem offset for element (m 0..127, k 0..15):
//   [part]*2048 + (k8*8 + m>>4)*128 + lane*4 + r
//   lane = ((m&7)<<2)|(k&3),  r = ((k>>2)&1)*2 + ((m>>3)&1)
__device__ __forceinline__ int a_off(int m, int k) {
    return ((k >> 3) * 8 + (m >> 4)) * 128
         + ((((m & 7) << 2) | (k & 3)) << 2)
         + (((k >> 2) & 1) << 1) + ((m >> 3) & 1);
}
// B-fragment offset for (n 0..127, k 0..15):
//   [part]*2048 + k8*1024 + (n>>3)*64 + lane*2 + r
//   lane = ((n&7)<<2)|(k&3),  r = (k>>2)&1
__device__ __forceinline__ int b_off(int n, int k) {
    return (((k >> 3) & 1) << 10) + ((n >> 3) << 6)
         + ((((n & 7) << 2) | (k & 3)) << 1) + ((k >> 2) & 1);
}

// ---------------------------------------------------------------------------
// Split kernels: produce fragment-ordered TF32-split B operands.
// ---------------------------------------------------------------------------
__global__ void splitW_kernel(const float* __restrict__ W) {
    for (int i = blockIdx.x * blockDim.x + threadIdx.x; i < DM * KCONV;
         i += gridDim.x * blockDim.x) {
        int n = i / KCONV, k = i % KCONV;
        float h, m; tf32_split(W[i], h, m);
        size_t base = ((size_t)(n >> 7) * NKB1 + (k >> 4)) * 4096;
        int off = b_off(n & 127, k & 15);
        g_Wfrag[base + off]        = h;
        g_Wfrag[base + 2048 + off] = m;
    }
}
__global__ void splitCB_kernel(const float* __restrict__ cb) {
    for (int i = blockIdx.x * blockDim.x + threadIdx.x; i < NBINS * DM;
         i += gridDim.x * blockDim.x) {
        int n = i / DM, k = i % DM;
        float h, m; tf32_split(cb[i], h, m);
        size_t base = ((size_t)(n >> 7) * NKB2 + (k >> 4)) * 4096;
        int off = b_off(n & 127, k & 15);
        g_CBfrag[base + off]        = h;
        g_CBfrag[base + 2048 + off] = m;
    }
}

// ---------------------------------------------------------------------------
// Codebook squared norms (exact fp32). One warp per row.
// ---------------------------------------------------------------------------
__global__ void cnorm_kernel(const float* __restrict__ cb) {
    int warp = (blockIdx.x * blockDim.x + threadIdx.x) >> 5;
    int lane = threadIdx.x & 31;
    if (warp >= NBINS) return;
    const float* row = cb + warp * DM;
    float s = 0.f;
    for (int i = lane; i < DM; i += 32) { float v = row[i]; s += v * v; }
    #pragma unroll
    for (int o = 16; o; o >>= 1) s += __shfl_xor_sync(0xffffffffu, s, o);
    if (lane == 0) g_cnorm[warp] = s;
}

// ---------------------------------------------------------------------------
// Shared compute step: one BK=16 chunk, 3-pass TF32 split.
// As: [part 2][2048] fragment-ordered A;  Bs: [part 2][2048] fragment-ordered B
// ---------------------------------------------------------------------------
__device__ __forceinline__ void mma_chunk(const float* As, const float* Bs,
                                          float acc[4][4][4], int mtb, int ntb,
                                          int lane) {
    #pragma unroll
    for (int k8 = 0; k8 < 2; ++k8) {
        uint4 ah[4], am[4]; uint2 bh[4], bm[4];
        #pragma unroll
        for (int t = 0; t < 4; ++t) {
            int base = (k8 * 8 + mtb + t) * 128 + lane * 4;
            ah[t] = *(const uint4*)&As[base];
            am[t] = *(const uint4*)&As[2048 + base];
        }
        #pragma unroll
        for (int t = 0; t < 4; ++t) {
            int base = k8 * 1024 + (ntb + t) * 64 + lane * 2;
            bh[t] = *(const uint2*)&Bs[base];
            bm[t] = *(const uint2*)&Bs[2048 + base];
        }
        #pragma unroll
        for (int i = 0; i < 4; ++i)
            #pragma unroll
            for (int j = 0; j < 4; ++j) {
                mma8(acc[i][j], (const u32*)&ah[i], (const u32*)&bh[j]);
                mma8(acc[i][j], (const u32*)&ah[i], (const u32*)&bm[j]);
                mma8(acc[i][j], (const u32*)&am[i], (const u32*)&bh[j]);
            }
    }
}

#define BUFSZ 8192   // floats per buffer: A 4096 + B 4096
#define SMEM_BYTES (2 * BUFSZ * 4)

// ---------------------------------------------------------------------------
// GEMM1: conv.  X[m=t'][n=d_out] = sum_k A[m][k] W[n][k] + bias[n]
//   A[m][2*d+tap] = ssl[d*TIN + 2*(m0+m) + tap]  (batch 0)
// Grid (64, 6), 256 threads, warp tile 64x32.
// ---------------------------------------------------------------------------
__global__ __launch_bounds__(256) void conv_tc(const float* __restrict__ ssl,
                                               const float* __restrict__ bias) {
    extern __shared__ float smf[];
    const int tid = threadIdx.x, lane = tid & 31, warp = tid >> 5;
    const int m0 = blockIdx.x * 128, n0 = blockIdx.y * 128;
    const int mtb = (warp >> 2) * 4, ntb = (warp & 3) * 4;

    float acc[4][4][4];
    #pragma unroll
    for (int i = 0; i < 4; ++i)
        #pragma unroll
        for (int j = 0; j < 4; ++j)
            #pragma unroll
            for (int c = 0; c < 4; ++c) acc[i][j][c] = 0.f;

    float2 va[4]; float4 vb[4];
    auto ldg = [&](int kb) {
        #pragma unroll
        for (int it = 0; it < 4; ++it) {
            int idx = tid + it * 256;           // 0..1023
            int m = idx & 127, dl = idx >> 7;   // dl 0..7
            va[it] = *(const float2*)(ssl + (size_t)(kb * 8 + dl) * TIN + 2 * (m0 + m));
        }
        const float4* src = (const float4*)(g_Wfrag +
            ((size_t)(n0 >> 7) * NKB1 + kb) * 4096);
        #pragma unroll
        for (int it = 0; it < 4; ++it) vb[it] = src[tid + it * 256];
    };
    auto sts = [&](float* buf) {
        float* As = buf; float* Bs = buf + 4096;
        #pragma unroll
        for (int it = 0; it < 4; ++it) {
            int idx = tid + it * 256;
            int m = idx & 127, dl = idx >> 7;
            float h, md;
            tf32_split(va[it].x, h, md);
            int o = a_off(m, 2 * dl);
            As[o] = h; As[2048 + o] = md;
            tf32_split(va[it].y, h, md);
            o = a_off(m, 2 * dl + 1);
            As[o] = h; As[2048 + o] = md;
        }
        #pragma unroll
        for (int it = 0; it < 4; ++it) ((float4*)Bs)[tid + it * 256] = vb[it];
    };

    ldg(0); sts(smf); __syncthreads();
    for (int kb = 0; kb < NKB1; ++kb) {
        int cur = kb & 1;
        bool more = (kb + 1 < NKB1);
        if (more) ldg(kb + 1);
        mma_chunk(smf + cur * BUFSZ, smf + cur * BUFSZ + 4096, acc, mtb, ntb, lane);
        if (more) {
            __syncthreads();
            sts(smf + (cur ^ 1) * BUFSZ);
            __syncthreads();
        }
    }

    // Epilogue: add bias, write X plain (float2 stores)
    const int gid = lane >> 2, tig = lane & 3;
    #pragma unroll
    for (int i = 0; i < 4; ++i) {
        int m = m0 + (warp >> 2) * 64 + i * 16 + gid;
        #pragma unroll
        for (int j = 0; j < 4; ++j) {
            int n = n0 + (warp & 3) * 32 + j * 8 + 2 * tig;
            float b0 = __ldg(&bias[n]), b1 = __ldg(&bias[n + 1]);
            *(float2*)&g_X[(size_t)m * DM + n] =
                make_float2(acc[i][j][0] + b0, acc[i][j][1] + b1);
            *(float2*)&g_X[(size_t)(m + 8) * DM + n] =
                make_float2(acc[i][j][2] + b0, acc[i][j][3] + b1);
        }
    }
}

// ---------------------------------------------------------------------------
// GEMM2: distance + fused argmin. dot[m][n] = sum_k X[m][k] cb[n][k];
// d2 = cnorm[n] - 2*dot (|x|^2 dropped). Grid (64, 8).
// ---------------------------------------------------------------------------
__global__ __launch_bounds__(256) void dist_tc() {
    extern __shared__ float smf[];
    const int tid = threadIdx.x, lane = tid & 31, warp = tid >> 5;
    const int m0 = blockIdx.x * 128, n0 = blockIdx.y * 128;
    const int mtb = (warp >> 2) * 4, ntb = (warp & 3) * 4;

    float acc[4][4][4];
    #pragma unroll
    for (int i = 0; i < 4; ++i)
        #pragma unroll
        for (int j = 0; j < 4; ++j)
            #pragma unroll
            for (int c = 0; c < 4; ++c) acc[i][j][c] = 0.f;

    float4 va[2]; float4 vb[4];
    auto ldg = [&](int kb) {
        #pragma unroll
        for (int it = 0; it < 2; ++it) {
            int idx = tid + it * 256;           // 0..511 float4s
            int row = idx >> 2, q = idx & 3;
            va[it] = *(const float4*)(g_X + (size_t)(m0 + row) * DM + kb * 16 + q * 4);
        }
        const float4* src = (const float4*)(g_CBfrag +
            ((size_t)(n0 >> 7) * NKB2 + kb) * 4096);
        #pragma unroll
        for (int it = 0; it < 4; ++it) vb[it] = src[tid + it * 256];
    };
    auto sts = [&](float* buf) {
        float* As = buf; float* Bs = buf + 4096;
        #pragma unroll
        for (int it = 0; it < 2; ++it) {
            int idx = tid + it * 256;
            int row = idx >> 2, q = idx & 3;
            float e[4] = { va[it].x, va[it].y, va[it].z, va[it].w };
            #pragma unroll
            for (int c = 0; c < 4; ++c) {
                float h, md; tf32_split(e[c], h, md);
                int o = a_off(row, q * 4 + c);
                As[o] = h; As[2048 + o] = md;
            }
        }
        #pragma unroll
        for (int it = 0; it < 4; ++it) ((float4*)Bs)[tid + it * 256] = vb[it];
    };

    ldg(0); sts(smf); __syncthreads();
    for (int kb = 0; kb < NKB2; ++kb) {
        int cur = kb & 1;
        bool more = (kb + 1 < NKB2);
        if (more) ldg(kb + 1);
        mma_chunk(smf + cur * BUFSZ, smf + cur * BUFSZ + 4096, acc, mtb, ntb, lane);
        if (more) {
            __syncthreads();
            sts(smf + (cur ^ 1) * BUFSZ);
            __syncthreads();
        }
    }
    __syncthreads();   // buffers now reusable for reduction

    float* redV = smf;                 // [128][4]
    int*   redI = (int*)(smf + 512);   // [128][4]
    const int gid = lane >> 2, tig = lane & 3;

    #pragma unroll
    for (int i = 0; i < 4; ++i) {
        #pragma unroll
        for (int h = 0; h < 2; ++h) {
            float bv = 3.4e38f; int bi = 1 << 30;
            #pragma unroll
            for (int j = 0; j < 4; ++j) {
                #pragma unroll
                for (int c = 0; c < 2; ++c) {
                    int n = n0 + (warp & 3) * 32 + j * 8 + 2 * tig + c;
                    float v = __ldg(&g_cnorm[n]) - 2.f * acc[i][j][h * 2 + c];
                    if (v < bv || (v == bv && n < bi)) { bv = v; bi = n; }
                }
            }
            // reduce across the 4 tig lanes (same gid)
            #pragma unroll
            for (int off = 2; off; off >>= 1) {
                float ov = __shfl_down_sync(0xffffffffu, bv, off, 4);
                int   oi = __shfl_down_sync(0xffffffffu, bi, off, 4);
                if (ov < bv || (ov == bv && oi < bi)) { bv = ov; bi = oi; }
            }
            if (tig == 0) {
                int ml = (warp >> 2) * 64 + i * 16 + h * 8 + gid;
                redV[ml * 4 + (warp & 3)] = bv;
                redI[ml * 4 + (warp & 3)] = bi;
            }
        }
    }
    __syncthreads();

    if (tid < 128) {
        float bv = redV[tid * 4]; int bi = redI[tid * 4];
        #pragma unroll
        for (int t = 1; t < 4; ++t) {
            float v = redV[tid * 4 + t]; int i2 = redI[tid * 4 + t];
            if (v < bv || (v == bv && i2 < bi)) { bv = v; bi = i2; }
        }
        g_pmin[(size_t)(m0 + tid) * 8 + blockIdx.y] = bv;
        g_pidx[(size_t)(m0 + tid) * 8 + blockIdx.y] = bi;
    }
}

// ---------------------------------------------------------------------------
// Final reduce over the 8 n-tiles per row (ascending n => first-min).
// Output written as float32 (harness dtype); indices < 2^24 exact.
// ---------------------------------------------------------------------------
__global__ void final_kernel(float* __restrict__ out) {
    int row = blockIdx.x * blockDim.x + threadIdx.x;
    if (row >= TQ) return;
    float bv = g_pmin[(size_t)row * 8];
    int   bi = g_pidx[(size_t)row * 8];
    #pragma unroll
    for (int t = 1; t < 8; ++t) {
        float v = g_pmin[(size_t)row * 8 + t];
        int   i = g_pidx[(size_t)row * 8 + t];
        if (v < bv || (v == bv && i < bi)) { bv = v; bi = i; }
    }
    out[row] = (float)bi;
}

// ---------------------------------------------------------------------------
// Launch. Inputs resolved BY ELEMENT COUNT (robust to metadata ordering).
// ---------------------------------------------------------------------------
static inline bool size_is(long long got, long long elems) {
    return got == elems || got == elems * 4;
}

extern "C" void kernel_launch(void* const* d_in, const int* in_sizes, int n_in,
                              void* d_out, int out_size) {
    const float* ssl  = nullptr;
    const float* W    = nullptr;
    const float* bias = nullptr;
    const float* cb   = nullptr;

    for (int i = 0; i < n_in; ++i) {
        long long s = (long long)in_sizes[i];
        if      (size_is(s, 8LL * 768 * 16384)) ssl  = (const float*)d_in[i];
        else if (size_is(s, 768LL * 768 * 2))   W    = (const float*)d_in[i];
        else if (size_is(s, 768LL))             bias = (const float*)d_in[i];
        else if (size_is(s, 1024LL * 768))      cb   = (const float*)d_in[i];
    }
    if (!ssl || !W || !bias || !cb) {
        ssl  = (const float*)d_in[0];
        W    = (const float*)d_in[1];
        bias = (const float*)d_in[2];
        cb   = (const float*)d_in[3];
    }
    float* out = (float*)d_out;

    static bool attr_done = false;
    if (!attr_done) {
        cudaFuncSetAttribute(conv_tc, cudaFuncAttributeMaxDynamicSharedMemorySize, SMEM_BYTES);
        cudaFuncSetAttribute(dist_tc, cudaFuncAttributeMaxDynamicSharedMemorySize, SMEM_BYTES);
        attr_done = true;
    }

    splitW_kernel <<<1024, 256>>>(W);
    splitCB_kernel<<<768, 256>>>(cb);
    cnorm_kernel  <<<128, 256>>>(cb);

    dim3 g1(TQ / 128, DM / 128);                 // 64 x 6
    conv_tc<<<g1, 256, SMEM_BYTES>>>(ssl, bias);

    dim3 g2(TQ / 128, NBINS / 128);              // 64 x 8
    dist_tc<<<g2, 256, SMEM_BYTES>>>();

    final_kernel<<<TQ / 256, 256>>>(out);
}

// round 10
// speedup vs baseline: 1.3728x; 1.3728x over previous
#include <cuda_runtime.h>
#include <cstdint>

// Problem constants
#define TQ     8192      // T/2 output positions
#define DM     768       // model dim
#define NBINS  1024      // codebook entries
#define TIN    16384     // input T
#define KCONV  1536      // conv GEMM K = D*2
#define NKB1   96        // conv K chunks (1536/16)
#define NKB2   48        // dist K chunks (768/16)

typedef unsigned int u32;

// ---------------------------------------------------------------------------
// Scratch (__device__ globals; no allocation).
// All operands pre-split to TF32 (hi, mid) AND pre-arranged in
// mma.m16n8k8 fragment order, so GEMM staging is a contiguous cp.async copy.
// Per (tile, kb) block: 4096 floats = [part(2)][2048 fragment-ordered].
// ---------------------------------------------------------------------------
__device__ float g_Afrag[64 * NKB1 * 4096];   // conv A   (100 MB)
__device__ float g_Wfrag [6 * NKB1 * 4096];   // conv B   (9.4 MB)
__device__ float g_Xfrag[64 * NKB2 * 4096];   // dist A = conv output (50 MB)
__device__ float g_CBfrag[8 * NKB2 * 4096];   // dist B   (6.3 MB)
__device__ float g_cnorm[NBINS];
__device__ float g_pmin[TQ * 8];
__device__ int   g_pidx[TQ * 8];

// ---------------------------------------------------------------------------
// Helpers (family-agnostic PTX only — build target is plain sm_103)
// ---------------------------------------------------------------------------
__device__ __forceinline__ void tf32_split(float x, float& h, float& m) {
    u32 hu, mu;
    asm("cvt.rna.tf32.f32 %0, %1;" : "=r"(hu) : "f"(x));
    h = __uint_as_float(hu);
    float r = x - h;
    asm("cvt.rna.tf32.f32 %0, %1;" : "=r"(mu) : "f"(r));
    m = __uint_as_float(mu);
}

__device__ __forceinline__ void mma8(float* d, const u32* a, const u32* b) {
    asm volatile(
        "mma.sync.aligned.m16n8k8.row.col.f32.tf32.tf32.f32 "
        "{%0,%1,%2,%3}, {%4,%5,%6,%7}, {%8,%9}, {%0,%1,%2,%3};"
        : "+f"(d[0]), "+f"(d[1]), "+f"(d[2]), "+f"(d[3])
        : "r"(a[0]), "r"(a[1]), "r"(a[2]), "r"(a[3]), "r"(b[0]), "r"(b[1]));
}

__device__ __forceinline__ u32 smem_u32(const void* p) {
    u32 a;
    asm("{ .reg .u64 t; cvta.to.shared.u64 t, %1; cvt.u32.u64 %0, t; }"
        : "=r"(a) : "l"(p));
    return a;
}
__device__ __forceinline__ void cpasync16(u32 dst, const void* src) {
    asm volatile("cp.async.cg.shared.global [%0], [%1], 16;"
                 :: "r"(dst), "l"(src) : "memory");
}
#define CP_COMMIT() asm volatile("cp.async.commit_group;" ::: "memory")
#define CP_WAIT(n)  asm volatile("cp.async.wait_group %0;" :: "n"(n) : "memory")

// A-fragment offset for (m 0..127, k 0..15):
//   (k8*8 + m>>4)*128 + lane*4 + r;  lane=((m&7)<<2)|(k&3), r=((k>>2)&1)*2+((m>>3)&1)
__device__ __forceinline__ int a_off(int m, int k) {
    return ((k >> 3) * 8 + (m >> 4)) * 128
         + ((((m & 7) << 2) | (k & 3)) << 2)
         + (((k >> 2) & 1) << 1) + ((m >> 3) & 1);
}
// B-fragment offset for (n 0..127, k 0..15):
//   k8*1024 + (n>>3)*64 + lane*2 + r;  lane=((n&7)<<2)|(k&3), r=(k>>2)&1
__device__ __forceinline__ int b_off(int n, int k) {
    return (((k >> 3) & 1) << 10) + ((n >> 3) << 6)
         + ((((n & 7) << 2) | (k & 3)) << 1) + ((k >> 2) & 1);
}

// ---------------------------------------------------------------------------
// Pre-pass kernels: build fragment-ordered TF32-split operands in gmem.
// ---------------------------------------------------------------------------
__global__ void splitW_kernel(const float* __restrict__ W) {
    for (int i = blockIdx.x * blockDim.x + threadIdx.x; i < DM * KCONV;
         i += gridDim.x * blockDim.x) {
        int n = i / KCONV, k = i % KCONV;
        float h, m; tf32_split(W[i], h, m);
        size_t base = ((size_t)(n >> 7) * NKB1 + (k >> 4)) * 4096;
        int off = b_off(n & 127, k & 15);
        g_Wfrag[base + off]        = h;
        g_Wfrag[base + 2048 + off] = m;
    }
}
__global__ void splitCB_kernel(const float* __restrict__ cb) {
    for (int i = blockIdx.x * blockDim.x + threadIdx.x; i < NBINS * DM;
         i += gridDim.x * blockDim.x) {
        int n = i / DM, k = i % DM;
        float h, m; tf32_split(cb[i], h, m);
        size_t base = ((size_t)(n >> 7) * NKB2 + (k >> 4)) * 4096;
        int off = b_off(n & 127, k & 15);
        g_CBfrag[base + off]        = h;
        g_CBfrag[base + 2048 + off] = m;
    }
}
// Conv A: A[m][2*d+tap] = ssl[d*TIN + 2*m + tap]  (batch 0). Coalesced over m.
__global__ void splitA_kernel(const float* __restrict__ ssl) {
    for (int i = blockIdx.x * blockDim.x + threadIdx.x; i < DM * TQ;
         i += gridDim.x * blockDim.x) {
        int d = i / TQ, m = i % TQ;
        const float2 v = *(const float2*)(ssl + (size_t)d * TIN + 2 * m);
        size_t mbase = (size_t)(m >> 7) * NKB1 * 4096;
        #pragma unroll
        for (int tap = 0; tap < 2; ++tap) {
            int k = 2 * d + tap;
            float h, md; tf32_split(tap ? v.y : v.x, h, md);
            size_t base = mbase + (size_t)(k >> 4) * 4096;
            int off = a_off(m & 127, k & 15);
            g_Afrag[base + off]        = h;
            g_Afrag[base + 2048 + off] = md;
        }
    }
}

// ---------------------------------------------------------------------------
// Codebook squared norms (exact fp32). One warp per row.
// ---------------------------------------------------------------------------
__global__ void cnorm_kernel(const float* __restrict__ cb) {
    int warp = (blockIdx.x * blockDim.x + threadIdx.x) >> 5;
    int lane = threadIdx.x & 31;
    if (warp >= NBINS) return;
    const float* row = cb + warp * DM;
    float s = 0.f;
    for (int i = lane; i < DM; i += 32) { float v = row[i]; s += v * v; }
    #pragma unroll
    for (int o = 16; o; o >>= 1) s += __shfl_xor_sync(0xffffffffu, s, o);
    if (lane == 0) g_cnorm[warp] = s;
}

// ---------------------------------------------------------------------------
// One BK=16 chunk, 3-pass TF32 split, warp tile 64x32.
// ---------------------------------------------------------------------------
__device__ __forceinline__ void mma_chunk(const float* As, const float* Bs,
                                          float acc[4][4][4], int mtb, int ntb,
                                          int lane) {
    #pragma unroll
    for (int k8 = 0; k8 < 2; ++k8) {
        uint4 ah[4], am[4]; uint2 bh[4], bm[4];
        #pragma unroll
        for (int t = 0; t < 4; ++t) {
            int base = (k8 * 8 + mtb + t) * 128 + lane * 4;
            ah[t] = *(const uint4*)&As[base];
            am[t] = *(const uint4*)&As[2048 + base];
        }
        #pragma unroll
        for (int t = 0; t < 4; ++t) {
            int base = k8 * 1024 + (ntb + t) * 64 + lane * 2;
            bh[t] = *(const uint2*)&Bs[base];
            bm[t] = *(const uint2*)&Bs[2048 + base];
        }
        #pragma unroll
        for (int i = 0; i < 4; ++i)
            #pragma unroll
            for (int j = 0; j < 4; ++j) {
                mma8(acc[i][j], (const u32*)&ah[i], (const u32*)&bh[j]);
                mma8(acc[i][j], (const u32*)&ah[i], (const u32*)&bm[j]);
                mma8(acc[i][j], (const u32*)&am[i], (const u32*)&bh[j]);
            }
    }
}

#define STAGES 4
#define STAGE_FLOATS 8192            // A 4096 + B 4096
#define STAGE_BYTES  32768
#define SMEM_BYTES   (STAGES * STAGE_BYTES)

// Issue one chunk's cp.async copies (A 16KB + B 16KB, contiguous).
__device__ __forceinline__ void issue_chunk(u32 smb, int s, int tid,
                                            const float* Ablk, const float* Bblk,
                                            int kb) {
    u32 sb = smb + s * STAGE_BYTES;
    const char* asrc = (const char*)Ablk + (size_t)kb * 16384;
    const char* bsrc = (const char*)Bblk + (size_t)kb * 16384;
    #pragma unroll
    for (int it = 0; it < 4; ++it) {
        int idx = tid + it * 256;
        cpasync16(sb + idx * 16,         asrc + (size_t)idx * 16);
        cpasync16(sb + 16384 + idx * 16, bsrc + (size_t)idx * 16);
    }
    CP_COMMIT();
}

// ---------------------------------------------------------------------------
// GEMM1: conv. Pure MMA mainloop. Epilogue: +bias, split, write g_Xfrag
// in dist-A fragment order. Grid (64, 6), 256 threads.
// ---------------------------------------------------------------------------
__global__ __launch_bounds__(256) void conv_tc(const float* __restrict__ bias) {
    extern __shared__ float smf[];
    const u32 smb = smem_u32(smf);
    const int tid = threadIdx.x, lane = tid & 31, warp = tid >> 5;
    const int m0 = blockIdx.x * 128, n0 = blockIdx.y * 128;
    const int mtb = (warp >> 2) * 4, ntb = (warp & 3) * 4;

    const float* Ablk = g_Afrag + (size_t)blockIdx.x * NKB1 * 4096;
    const float* Bblk = g_Wfrag + (size_t)blockIdx.y * NKB1 * 4096;

    float acc[4][4][4];
    #pragma unroll
    for (int i = 0; i < 4; ++i)
        #pragma unroll
        for (int j = 0; j < 4; ++j)
            #pragma unroll
            for (int c = 0; c < 4; ++c) acc[i][j][c] = 0.f;

    #pragma unroll
    for (int s = 0; s < STAGES - 1; ++s) issue_chunk(smb, s, tid, Ablk, Bblk, s);

    for (int kb = 0; kb < NKB1; ++kb) {
        CP_WAIT(STAGES - 2);
        __syncthreads();
        const float* buf = smf + (kb % STAGES) * STAGE_FLOATS;
        mma_chunk(buf, buf + 4096, acc, mtb, ntb, lane);
        int nk = kb + STAGES - 1;
        if (nk < NKB1) issue_chunk(smb, nk % STAGES, tid, Ablk, Bblk, nk);
    }
    CP_WAIT(0);

    // Epilogue: add bias, tf32-split, scatter into dist-A fragment layout.
    const int gid = lane >> 2, tig = lane & 3;
    const size_t xmb = (size_t)blockIdx.x * NKB2 * 4096;   // m-tile base
    #pragma unroll
    for (int i = 0; i < 4; ++i) {
        #pragma unroll
        for (int c = 0; c < 4; ++c) {
            int m = (warp >> 2) * 64 + i * 16 + gid + ((c >> 1) << 3); // local m
            #pragma unroll
            for (int j = 0; j < 4; ++j) {
                int n = n0 + (warp & 3) * 32 + j * 8 + 2 * tig + (c & 1); // global d
                float x = acc[i][j][c] + __ldg(&bias[n]);
                float h, md; tf32_split(x, h, md);
                size_t base = xmb + (size_t)(n >> 4) * 4096;
                int off = a_off(m, n & 15);
                g_Xfrag[base + off]        = h;
                g_Xfrag[base + 2048 + off] = md;
            }
        }
    }
    (void)m0;
}

// ---------------------------------------------------------------------------
// GEMM2: distance + fused argmin. Pure MMA mainloop. Grid (64, 8).
// ---------------------------------------------------------------------------
__global__ __launch_bounds__(256) void dist_tc() {
    extern __shared__ float smf[];
    const u32 smb = smem_u32(smf);
    const int tid = threadIdx.x, lane = tid & 31, warp = tid >> 5;
    const int m0 = blockIdx.x * 128, n0 = blockIdx.y * 128;
    const int mtb = (warp >> 2) * 4, ntb = (warp & 3) * 4;

    const float* Ablk = g_Xfrag  + (size_t)blockIdx.x * NKB2 * 4096;
    const float* Bblk = g_CBfrag + (size_t)blockIdx.y * NKB2 * 4096;

    float acc[4][4][4];
    #pragma unroll
    for (int i = 0; i < 4; ++i)
        #pragma unroll
        for (int j = 0; j < 4; ++j)
            #pragma unroll
            for (int c = 0; c < 4; ++c) acc[i][j][c] = 0.f;

    #pragma unroll
    for (int s = 0; s < STAGES - 1; ++s) issue_chunk(smb, s, tid, Ablk, Bblk, s);

    for (int kb = 0; kb < NKB2; ++kb) {
        CP_WAIT(STAGES - 2);
        __syncthreads();
        const float* buf = smf + (kb % STAGES) * STAGE_FLOATS;
        mma_chunk(buf, buf + 4096, acc, mtb, ntb, lane);
        int nk = kb + STAGES - 1;
        if (nk < NKB2) issue_chunk(smb, nk % STAGES, tid, Ablk, Bblk, nk);
    }
    CP_WAIT(0);
    __syncthreads();                      // buffers reusable for reduction

    float* redV = smf;                    // [128][4]
    int*   redI = (int*)(smf + 512);      // [128][4]
    const int gid = lane >> 2, tig = lane & 3;

    #pragma unroll
    for (int i = 0; i < 4; ++i) {
        #pragma unroll
        for (int h = 0; h < 2; ++h) {
            float bv = 3.4e38f; int bi = 1 << 30;
            #pragma unroll
            for (int j = 0; j < 4; ++j) {
                #pragma unroll
                for (int c = 0; c < 2; ++c) {
                    int n = n0 + (warp & 3) * 32 + j * 8 + 2 * tig + c;
                    float v = __ldg(&g_cnorm[n]) - 2.f * acc[i][j][h * 2 + c];
                    if (v < bv || (v == bv && n < bi)) { bv = v; bi = n; }
                }
            }
            #pragma unroll
            for (int off = 2; off; off >>= 1) {
                float ov = __shfl_down_sync(0xffffffffu, bv, off, 4);
                int   oi = __shfl_down_sync(0xffffffffu, bi, off, 4);
                if (ov < bv || (ov == bv && oi < bi)) { bv = ov; bi = oi; }
            }
            if (tig == 0) {
                int ml = (warp >> 2) * 64 + i * 16 + h * 8 + gid;
                redV[ml * 4 + (warp & 3)] = bv;
                redI[ml * 4 + (warp & 3)] = bi;
            }
        }
    }
    __syncthreads();

    if (tid < 128) {
        float bv = redV[tid * 4]; int bi = redI[tid * 4];
        #pragma unroll
        for (int t = 1; t < 4; ++t) {
            float v = redV[tid * 4 + t]; int i2 = redI[tid * 4 + t];
            if (v < bv || (v == bv && i2 < bi)) { bv = v; bi = i2; }
        }
        g_pmin[(size_t)(m0 + tid) * 8 + blockIdx.y] = bv;
        g_pidx[(size_t)(m0 + tid) * 8 + blockIdx.y] = bi;
    }
}

// ---------------------------------------------------------------------------
// Final reduce over the 8 n-tiles per row (lowest index wins ties).
// Output as float32 (harness dtype); indices < 2^24 exact.
// ---------------------------------------------------------------------------
__global__ void final_kernel(float* __restrict__ out) {
    int row = blockIdx.x * blockDim.x + threadIdx.x;
    if (row >= TQ) return;
    float bv = g_pmin[(size_t)row * 8];
    int   bi = g_pidx[(size_t)row * 8];
    #pragma unroll
    for (int t = 1; t < 8; ++t) {
        float v = g_pmin[(size_t)row * 8 + t];
        int   i = g_pidx[(size_t)row * 8 + t];
        if (v < bv || (v == bv && i < bi)) { bv = v; bi = i; }
    }
    out[row] = (float)bi;
}

// ---------------------------------------------------------------------------
// Launch. Inputs resolved BY ELEMENT COUNT (robust to metadata ordering).
// ---------------------------------------------------------------------------
static inline bool size_is(long long got, long long elems) {
    return got == elems || got == elems * 4;
}

extern "C" void kernel_launch(void* const* d_in, const int* in_sizes, int n_in,
                              void* d_out, int out_size) {
    const float* ssl  = nullptr;
    const float* W    = nullptr;
    const float* bias = nullptr;
    const float* cb   = nullptr;

    for (int i = 0; i < n_in; ++i) {
        long long s = (long long)in_sizes[i];
        if      (size_is(s, 8LL * 768 * 16384)) ssl  = (const float*)d_in[i];
        else if (size_is(s, 768LL * 768 * 2))   W    = (const float*)d_in[i];
        else if (size_is(s, 768LL))             bias = (const float*)d_in[i];
        else if (size_is(s, 1024LL * 768))      cb   = (const float*)d_in[i];
    }
    if (!ssl || !W || !bias || !cb) {
        ssl  = (const float*)d_in[0];
        W    = (const float*)d_in[1];
        bias = (const float*)d_in[2];
        cb   = (const float*)d_in[3];
    }
    float* out = (float*)d_out;

    static bool attr_done = false;
    if (!attr_done) {
        cudaFuncSetAttribute(conv_tc, cudaFuncAttributeMaxDynamicSharedMemorySize, SMEM_BYTES);
        cudaFuncSetAttribute(dist_tc, cudaFuncAttributeMaxDynamicSharedMemorySize, SMEM_BYTES);
        attr_done = true;
    }

    splitW_kernel <<<1024, 256>>>(W);
    splitCB_kernel<<<768, 256>>>(cb);
    splitA_kernel <<<12288, 256>>>(ssl);
    cnorm_kernel  <<<128, 256>>>(cb);

    dim3 g1(TQ / 128, DM / 128);                 // 64 x 6
    conv_tc<<<g1, 256, SMEM_BYTES>>>(bias);

    dim3 g2(TQ / 128, NBINS / 128);              // 64 x 8
    dist_tc<<<g2, 256, SMEM_BYTES>>>();

    final_kernel<<<TQ / 256, 256>>>(out);
}

// round 12
// speedup vs baseline: 1.5048x; 1.0961x over previous
#include <cuda_runtime.h>
#include <cstdint>

// Problem constants
#define TQ     8192      // T/2 output positions
#define DM     768       // model dim
#define NBINS  1024      // codebook entries
#define TIN    16384     // input T
#define KCONV  1536      // conv GEMM K = D*2
#define NKB1   96        // conv K chunks (1536/16)
#define NKB2   48        // dist K chunks (768/16)

typedef unsigned int u32;

// ---------------------------------------------------------------------------
// Scratch (__device__ globals; no allocation).
// All operands pre-split to TF32 (hi, mid) AND pre-arranged in
// mma.m16n8k8 fragment order, so GEMM staging is a contiguous cp.async copy.
// Per (tile, kb) block: 4096 floats = [part(2)][2048 fragment-ordered].
// ---------------------------------------------------------------------------
__device__ float g_Afrag[64 * NKB1 * 4096];   // conv A   (100 MB)
__device__ float g_Wfrag [6 * NKB1 * 4096];   // conv B   (9.4 MB)
__device__ float g_Xfrag[64 * NKB2 * 4096];   // dist A = conv output (50 MB)
__device__ float g_CBfrag[8 * NKB2 * 4096];   // dist B   (6.3 MB)
__device__ float g_cnorm[NBINS];
__device__ float g_pmin[TQ * 8];
__device__ int   g_pidx[TQ * 8];

// ---------------------------------------------------------------------------
// Helpers (family-agnostic PTX only — build target is plain sm_103)
// ---------------------------------------------------------------------------
__device__ __forceinline__ void tf32_split(float x, float& h, float& m) {
    u32 hu, mu;
    asm("cvt.rna.tf32.f32 %0, %1;" : "=r"(hu) : "f"(x));
    h = __uint_as_float(hu);
    float r = x - h;
    asm("cvt.rna.tf32.f32 %0, %1;" : "=r"(mu) : "f"(r));
    m = __uint_as_float(mu);
}

__device__ __forceinline__ void mma8(float* d, const u32* a, const u32* b) {
    asm volatile(
        "mma.sync.aligned.m16n8k8.row.col.f32.tf32.tf32.f32 "
        "{%0,%1,%2,%3}, {%4,%5,%6,%7}, {%8,%9}, {%0,%1,%2,%3};"
        : "+f"(d[0]), "+f"(d[1]), "+f"(d[2]), "+f"(d[3])
        : "r"(a[0]), "r"(a[1]), "r"(a[2]), "r"(a[3]), "r"(b[0]), "r"(b[1]));
}

__device__ __forceinline__ u32 smem_u32(const void* p) {
    u32 a;
    asm("{ .reg .u64 t; cvta.to.shared.u64 t, %1; cvt.u32.u64 %0, t; }"
        : "=r"(a) : "l"(p));
    return a;
}
__device__ __forceinline__ void cpasync16(u32 dst, const void* src) {
    asm volatile("cp.async.cg.shared.global [%0], [%1], 16;"
                 :: "r"(dst), "l"(src) : "memory");
}
#define CP_COMMIT() asm volatile("cp.async.commit_group;" ::: "memory")
#define CP_WAIT(n)  asm volatile("cp.async.wait_group %0;" :: "n"(n) : "memory")

// A-fragment offset for (m 0..127, k 0..15):
//   (k8*8 + m>>4)*128 + lane*4 + r;  lane=((m&7)<<2)|(k&3), r=((k>>2)&1)*2+((m>>3)&1)
__device__ __forceinline__ int a_off(int m, int k) {
    return ((k >> 3) * 8 + (m >> 4)) * 128
         + ((((m & 7) << 2) | (k & 3)) << 2)
         + (((k >> 2) & 1) << 1) + ((m >> 3) & 1);
}
// B-fragment offset for (n 0..127, k 0..15):
//   k8*1024 + (n>>3)*64 + lane*2 + r;  lane=((n&7)<<2)|(k&3), r=(k>>2)&1
__device__ __forceinline__ int b_off(int n, int k) {
    return (((k >> 3) & 1) << 10) + ((n >> 3) << 6)
         + ((((n & 7) << 2) | (k & 3)) << 1) + ((k >> 2) & 1);
}

// ---------------------------------------------------------------------------
// Pre-pass kernels: build fragment-ordered TF32-split operands in gmem.
// ---------------------------------------------------------------------------
__global__ void splitW_kernel(const float* __restrict__ W) {
    for (int i = blockIdx.x * blockDim.x + threadIdx.x; i < DM * KCONV;
         i += gridDim.x * blockDim.x) {
        int n = i / KCONV, k = i % KCONV;
        float h, m; tf32_split(W[i], h, m);
        size_t base = ((size_t)(n >> 7) * NKB1 + (k >> 4)) * 4096;
        int off = b_off(n & 127, k & 15);
        g_Wfrag[base + off]        = h;
        g_Wfrag[base + 2048 + off] = m;
    }
}
__global__ void splitCB_kernel(const float* __restrict__ cb) {
    for (int i = blockIdx.x * blockDim.x + threadIdx.x; i < NBINS * DM;
         i += gridDim.x * blockDim.x) {
        int n = i / DM, k = i % DM;
        float h, m; tf32_split(cb[i], h, m);
        size_t base = ((size_t)(n >> 7) * NKB2 + (k >> 4)) * 4096;
        int off = b_off(n & 127, k & 15);
        g_CBfrag[base + off]        = h;
        g_CBfrag[base + 2048 + off] = m;
    }
}
// Conv A: A[m][2*d+tap] = ssl[d*TIN + 2*m + tap]  (batch 0). Coalesced over m.
__global__ void splitA_kernel(const float* __restrict__ ssl) {
    for (int i = blockIdx.x * blockDim.x + threadIdx.x; i < DM * TQ;
         i += gridDim.x * blockDim.x) {
        int d = i / TQ, m = i % TQ;
        const float2 v = *(const float2*)(ssl + (size_t)d * TIN + 2 * m);
        size_t mbase = (size_t)(m >> 7) * NKB1 * 4096;
        #pragma unroll
        for (int tap = 0; tap < 2; ++tap) {
            int k = 2 * d + tap;
            float h, md; tf32_split(tap ? v.y : v.x, h, md);
            size_t base = mbase + (size_t)(k >> 4) * 4096;
            int off = a_off(m & 127, k & 15);
            g_Afrag[base + off]        = h;
            g_Afrag[base + 2048 + off] = md;
        }
    }
}

// ---------------------------------------------------------------------------
// Codebook squared norms (exact fp32). One warp per row.
// ---------------------------------------------------------------------------
__global__ void cnorm_kernel(const float* __restrict__ cb) {
    int warp = (blockIdx.x * blockDim.x + threadIdx.x) >> 5;
    int lane = threadIdx.x & 31;
    if (warp >= NBINS) return;
    const float* row = cb + warp * DM;
    float s = 0.f;
    for (int i = lane; i < DM; i += 32) { float v = row[i]; s += v * v; }
    #pragma unroll
    for (int o = 16; o; o >>= 1) s += __shfl_xor_sync(0xffffffffu, s, o);
    if (lane == 0) g_cnorm[warp] = s;
}

// ---------------------------------------------------------------------------
// One BK=16 chunk, 3-pass TF32 split, warp tile 64x32.
// Passes issued grouped (hh x16, hm x16, mh x16) so 16 independent
// accumulators separate dependent reuses of each acc register.
// ---------------------------------------------------------------------------
__device__ __forceinline__ void mma_chunk(const float* As, const float* Bs,
                                          float acc[4][4][4], int mtb, int ntb,
                                          int lane) {
    #pragma unroll
    for (int k8 = 0; k8 < 2; ++k8) {
        uint4 ah[4], am[4]; uint2 bh[4], bm[4];
        #pragma unroll
        for (int t = 0; t < 4; ++t) {
            int base = (k8 * 8 + mtb + t) * 128 + lane * 4;
            ah[t] = *(const uint4*)&As[base];
            am[t] = *(const uint4*)&As[2048 + base];
        }
        #pragma unroll
        for (int t = 0; t < 4; ++t) {
            int base = k8 * 1024 + (ntb + t) * 64 + lane * 2;
            bh[t] = *(const uint2*)&Bs[base];
            bm[t] = *(const uint2*)&Bs[2048 + base];
        }
        #pragma unroll
        for (int i = 0; i < 4; ++i)
            #pragma unroll
            for (int j = 0; j < 4; ++j)
                mma8(acc[i][j], (const u32*)&ah[i], (const u32*)&bh[j]);
        #pragma unroll
        for (int i = 0; i < 4; ++i)
            #pragma unroll
            for (int j = 0; j < 4; ++j)
                mma8(acc[i][j], (const u32*)&ah[i], (const u32*)&bm[j]);
        #pragma unroll
        for (int i = 0; i < 4; ++i)
            #pragma unroll
            for (int j = 0; j < 4; ++j)
                mma8(acc[i][j], (const u32*)&am[i], (const u32*)&bh[j]);
    }
}

#define STAGES 3
#define STAGE_FLOATS 8192            // A 4096 + B 4096
#define STAGE_BYTES  32768
#define SMEM_BYTES   (STAGES * STAGE_BYTES)   // 96 KB -> 2 CTAs/SM

// Issue one chunk's cp.async copies (A 16KB + B 16KB, contiguous).
__device__ __forceinline__ void issue_chunk(u32 smb, int s, int tid,
                                            const float* Ablk, const float* Bblk,
                                            int kb) {
    u32 sb = smb + s * STAGE_BYTES;
    const char* asrc = (const char*)Ablk + (size_t)kb * 16384;
    const char* bsrc = (const char*)Bblk + (size_t)kb * 16384;
    #pragma unroll
    for (int it = 0; it < 4; ++it) {
        int idx = tid + it * 256;
        cpasync16(sb + idx * 16,         asrc + (size_t)idx * 16);
        cpasync16(sb + 16384 + idx * 16, bsrc + (size_t)idx * 16);
    }
    CP_COMMIT();
}

// ---------------------------------------------------------------------------
// GEMM1: conv. Pure MMA mainloop. Grid (6 n-tiles, 64 m-tiles): consecutive
// bids share the A-tile (L2 reuse). Epilogue: +bias, split, write g_Xfrag.
// ---------------------------------------------------------------------------
__global__ __launch_bounds__(256, 2) void conv_tc(const float* __restrict__ bias) {
    extern __shared__ float smf[];
    const u32 smb = smem_u32(smf);
    const int tid = threadIdx.x, lane = tid & 31, warp = tid >> 5;
    const int ntile = blockIdx.x, mtile = blockIdx.y;
    const int n0 = ntile * 128;
    const int mtb = (warp >> 2) * 4, ntb = (warp & 3) * 4;

    const float* Ablk = g_Afrag + (size_t)mtile * NKB1 * 4096;
    const float* Bblk = g_Wfrag + (size_t)ntile * NKB1 * 4096;

    float acc[4][4][4];
    #pragma unroll
    for (int i = 0; i < 4; ++i)
        #pragma unroll
        for (int j = 0; j < 4; ++j)
            #pragma unroll
            for (int c = 0; c < 4; ++c) acc[i][j][c] = 0.f;

    #pragma unroll
    for (int s = 0; s < STAGES - 1; ++s) issue_chunk(smb, s, tid, Ablk, Bblk, s);

    for (int kb = 0; kb < NKB1; ++kb) {
        CP_WAIT(STAGES - 2);
        __syncthreads();
        const float* buf = smf + (kb % STAGES) * STAGE_FLOATS;
        mma_chunk(buf, buf + 4096, acc, mtb, ntb, lane);
        int nk = kb + STAGES - 1;
        if (nk < NKB1) issue_chunk(smb, nk % STAGES, tid, Ablk, Bblk, nk);
    }
    CP_WAIT(0);

    // Epilogue: add bias, tf32-split, scatter into dist-A fragment layout.
    const int gid = lane >> 2, tig = lane & 3;
    const size_t xmb = (size_t)mtile * NKB2 * 4096;   // m-tile base
    #pragma unroll
    for (int i = 0; i < 4; ++i) {
        #pragma unroll
        for (int c = 0; c < 4; ++c) {
            int m = (warp >> 2) * 64 + i * 16 + gid + ((c >> 1) << 3); // local m
            #pragma unroll
            for (int j = 0; j < 4; ++j) {
                int n = n0 + (warp & 3) * 32 + j * 8 + 2 * tig + (c & 1); // global d
                float x = acc[i][j][c] + __ldg(&bias[n]);
                float h, md; tf32_split(x, h, md);
                size_t base = xmb + (size_t)(n >> 4) * 4096;
                int off = a_off(m, n & 15);
                g_Xfrag[base + off]        = h;
                g_Xfrag[base + 2048 + off] = md;
            }
        }
    }
}

// ---------------------------------------------------------------------------
// GEMM2: distance + fused argmin. Grid (8 n-tiles, 64 m-tiles).
// ---------------------------------------------------------------------------
__global__ __launch_bounds__(256, 2) void dist_tc() {
    extern __shared__ float smf[];
    const u32 smb = smem_u32(smf);
    const int tid = threadIdx.x, lane = tid & 31, warp = tid >> 5;
    const int ntile = blockIdx.x, mtile = blockIdx.y;
    const int m0 = mtile * 128, n0 = ntile * 128;
    const int mtb = (warp >> 2) * 4, ntb = (warp & 3) * 4;

    const float* Ablk = g_Xfrag  + (size_t)mtile * NKB2 * 4096;
    const float* Bblk = g_CBfrag + (size_t)ntile * NKB2 * 4096;

    float acc[4][4][4];
    #pragma unroll
    for (int i = 0; i < 4; ++i)
        #pragma unroll
        for (int j = 0; j < 4; ++j)
            #pragma unroll
            for (int c = 0; c < 4; ++c) acc[i][j][c] = 0.f;

    #pragma unroll
    for (int s = 0; s < STAGES - 1; ++s) issue_chunk(smb, s, tid, Ablk, Bblk, s);

    for (int kb = 0; kb < NKB2; ++kb) {
        CP_WAIT(STAGES - 2);
        __syncthreads();
        const float* buf = smf + (kb % STAGES) * STAGE_FLOATS;
        mma_chunk(buf, buf + 4096, acc, mtb, ntb, lane);
        int nk = kb + STAGES - 1;
        if (nk < NKB2) issue_chunk(smb, nk % STAGES, tid, Ablk, Bblk, nk);
    }
    CP_WAIT(0);
    __syncthreads();                      // buffers reusable for reduction

    float* redV = smf;                    // [128][4]
    int*   redI = (int*)(smf + 512);      // [128][4]
    const int gid = lane >> 2, tig = lane & 3;

    #pragma unroll
    for (int i = 0; i < 4; ++i) {
        #pragma unroll
        for (int h = 0; h < 2; ++h) {
            float bv = 3.4e38f; int bi = 1 << 30;
            #pragma unroll
            for (int j = 0; j < 4; ++j) {
                #pragma unroll
                for (int c = 0; c < 2; ++c) {
                    int n = n0 + (warp & 3) * 32 + j * 8 + 2 * tig + c;
                    float v = __ldg(&g_cnorm[n]) - 2.f * acc[i][j][h * 2 + c];
                    if (v < bv || (v == bv && n < bi)) { bv = v; bi = n; }
                }
            }
            #pragma unroll
            for (int off = 2; off; off >>= 1) {
                float ov = __shfl_down_sync(0xffffffffu, bv, off, 4);
                int   oi = __shfl_down_sync(0xffffffffu, bi, off, 4);
                if (ov < bv || (ov == bv && oi < bi)) { bv = ov; bi = oi; }
            }
            if (tig == 0) {
                int ml = (warp >> 2) * 64 + i * 16 + h * 8 + gid;
                redV[ml * 4 + (warp & 3)] = bv;
                redI[ml * 4 + (warp & 3)] = bi;
            }
        }
    }
    __syncthreads();

    if (tid < 128) {
        float bv = redV[tid * 4]; int bi = redI[tid * 4];
        #pragma unroll
        for (int t = 1; t < 4; ++t) {
            float v = redV[tid * 4 + t]; int i2 = redI[tid * 4 + t];
            if (v < bv || (v == bv && i2 < bi)) { bv = v; bi = i2; }
        }
        g_pmin[(size_t)(m0 + tid) * 8 + ntile] = bv;
        g_pidx[(size_t)(m0 + tid) * 8 + ntile] = bi;
    }
}

// ---------------------------------------------------------------------------
// Final reduce over the 8 n-tiles per row (lowest index wins ties).
// Output as float32 (harness dtype); indices < 2^24 exact.
// ---------------------------------------------------------------------------
__global__ void final_kernel(float* __restrict__ out) {
    int row = blockIdx.x * blockDim.x + threadIdx.x;
    if (row >= TQ) return;
    float bv = g_pmin[(size_t)row * 8];
    int   bi = g_pidx[(size_t)row * 8];
    #pragma unroll
    for (int t = 1; t < 8; ++t) {
        float v = g_pmin[(size_t)row * 8 + t];
        int   i = g_pidx[(size_t)row * 8 + t];
        if (v < bv || (v == bv && i < bi)) { bv = v; bi = i; }
    }
    out[row] = (float)bi;
}

// ---------------------------------------------------------------------------
// Launch. Inputs resolved BY ELEMENT COUNT (robust to metadata ordering).
// ---------------------------------------------------------------------------
static inline bool size_is(long long got, long long elems) {
    return got == elems || got == elems * 4;
}

extern "C" void kernel_launch(void* const* d_in, const int* in_sizes, int n_in,
                              void* d_out, int out_size) {
    const float* ssl  = nullptr;
    const float* W    = nullptr;
    const float* bias = nullptr;
    const float* cb   = nullptr;

    for (int i = 0; i < n_in; ++i) {
        long long s = (long long)in_sizes[i];
        if      (size_is(s, 8LL * 768 * 16384)) ssl  = (const float*)d_in[i];
        else if (size_is(s, 768LL * 768 * 2))   W    = (const float*)d_in[i];
        else if (size_is(s, 768LL))             bias = (const float*)d_in[i];
        else if (size_is(s, 1024LL * 768))      cb   = (const float*)d_in[i];
    }
    if (!ssl || !W || !bias || !cb) {
        ssl  = (const float*)d_in[0];
        W    = (const float*)d_in[1];
        bias = (const float*)d_in[2];
        cb   = (const float*)d_in[3];
    }
    float* out = (float*)d_out;

    static bool attr_done = false;
    if (!attr_done) {
        cudaFuncSetAttribute(conv_tc, cudaFuncAttributeMaxDynamicSharedMemorySize, SMEM_BYTES);
        cudaFuncSetAttribute(dist_tc, cudaFuncAttributeMaxDynamicSharedMemorySize, SMEM_BYTES);
        attr_done = true;
    }

    splitW_kernel <<<1024, 256>>>(W);
    splitCB_kernel<<<768, 256>>>(cb);
    splitA_kernel <<<12288, 256>>>(ssl);
    cnorm_kernel  <<<128, 256>>>(cb);

    dim3 g1(DM / 128, TQ / 128);                 // (6 n-tiles, 64 m-tiles)
    conv_tc<<<g1, 256, SMEM_BYTES>>>(bias);

    dim3 g2(NBINS / 128, TQ / 128);              // (8 n-tiles, 64 m-tiles)
    dist_tc<<<g2, 256, SMEM_BYTES>>>();

    final_kernel<<<TQ / 256, 256>>>(out);
}